// round 13
// baseline (speedup 1.0000x reference)
#include <cuda_runtime.h>
#include <cstdint>

namespace {

constexpr int Bz  = 4;
constexpr int NHn = 4;
constexpr int Tn  = 512;
constexpr int Dn  = 256;
constexpr int Nn  = 8192;
constexpr int BHn = Bz * NHn;
constexpr float SCALEF = 0.011048543456039806f;  // N^-0.5

// Scratch (device globals; allocation-free). All values tf32-pre-rounded fp32.
__device__ float g_qr[(size_t)BHn * Tn * Nn];   // RoPE(Q)    (t,n)
__device__ float g_qt[(size_t)BHn * Nn * Tn];   // RoPE(Q)^T  (n,t)
__device__ float g_st[(size_t)BHn * Dn * Nn];   // state^T    (d,n)
__device__ float g_vt[(size_t)Bz * Dn * Tn];    // V^T        (d,t)
__device__ float g_sc[(size_t)BHn * Tn * Tn];   // masked scores (t,s)
__device__ float g_oa[(size_t)BHn * Tn * Dn];   // partial out: QR @ state

// Lower-tri tile enumeration (10 tiles per bh for 4x4 tile grid)
__device__ const int TRI_T[10] = {0, 1, 1, 2, 2, 2, 3, 3, 3, 3};
__device__ const int TRI_S[10] = {0, 0, 1, 0, 1, 2, 0, 1, 2, 3};

// ---------------------------------------------------------------------------
// Tiling: BM=BN=128, BK=32. SMEM tiles [128 rows][36 words].
// 8 warps as 2(m) x 4(n); warp tile 64x32. 3-stage cp.async pipeline,
// 2 CTAs per SM.
// ---------------------------------------------------------------------------
constexpr int BM = 128, BK = 32;
constexpr int RSTR = 36;
constexpr int TILE_WORDS = BM * RSTR;            // 4608
constexpr int STG = 3;
constexpr int SMEM_TOTAL = STG * 2 * TILE_WORDS * 4;   // 110592 B

__device__ __forceinline__ uint32_t f2t(float x) {
    uint32_t u;
    asm("cvt.rna.tf32.f32 %0, %1;" : "=r"(u) : "f"(x));
    return u;
}
__device__ __forceinline__ float f2tf(float x) { return __uint_as_float(f2t(x)); }

__device__ __forceinline__ uint32_t smem_u32(const void* p) {
    uint32_t a;
    asm("{ .reg .u64 t; cvta.to.shared.u64 t, %1; cvt.u32.u64 %0, t; }"
        : "=r"(a) : "l"(p));
    return a;
}

__device__ __forceinline__ void mma_tf32(float c[4], const uint32_t a[4],
                                         const uint32_t b[2]) {
    asm volatile(
        "mma.sync.aligned.m16n8k8.row.col.f32.tf32.tf32.f32 "
        "{%0,%1,%2,%3}, {%4,%5,%6,%7}, {%8,%9}, {%0,%1,%2,%3};"
        : "+f"(c[0]), "+f"(c[1]), "+f"(c[2]), "+f"(c[3])
        : "r"(a[0]), "r"(a[1]), "r"(a[2]), "r"(a[3]), "r"(b[0]), "r"(b[1]));
}

// One k-octet of the 64x32 warp tile. A,B both [128][36] row-major.
__device__ __forceinline__ void mma_oct(const uint32_t* __restrict__ As,
                                        const uint32_t* __restrict__ Bs,
                                        int ko, int wm, int wn,
                                        int gid, int tig, float c[16][4]) {
    uint32_t a[4][4], b[4][2];
#pragma unroll
    for (int im = 0; im < 4; ++im) {
        const uint32_t* pa = As + (wm + im * 16 + gid) * RSTR + ko + tig;
        a[im][0] = pa[0];
        a[im][1] = pa[8 * RSTR];
        a[im][2] = pa[4];
        a[im][3] = pa[8 * RSTR + 4];
    }
#pragma unroll
    for (int jn = 0; jn < 4; ++jn) {
        const uint32_t* pb = Bs + (wn + jn * 8 + gid) * RSTR + ko + tig;
        b[jn][0] = pb[0];
        b[jn][1] = pb[4];
    }
#pragma unroll
    for (int im = 0; im < 4; ++im)
#pragma unroll
        for (int jn = 0; jn < 4; ++jn)
            mma_tf32(c[im * 4 + jn], a[im], b[jn]);
}

// cp.async one [128][32] fp32 tile (k contiguous in source, row stride ld).
__device__ __forceinline__ void cp_tile(uint32_t dbase,
                                        const float* __restrict__ src, int ld) {
#pragma unroll
    for (int i = 0; i < 4; ++i) {
        int ch = threadIdx.x + i * 256;
        int row = ch >> 3, kc = (ch & 7) * 4;
        uint32_t d = dbase + (uint32_t)((row * RSTR + kc) * 4);
        asm volatile("cp.async.cg.shared.global [%0], [%1], 16;"
                     :: "r"(d), "l"(src + (size_t)row * ld + kc));
    }
}
#define CP_COMMIT() asm volatile("cp.async.commit_group;" ::: "memory")
#define CP_WAIT1()  asm volatile("cp.async.wait_group 1;" ::: "memory")

// ---------------------------------------------------------------------------
// Shared GEMM mainloop driver. Fetch(kt) -> {A ptr, lda, B ptr, ldb}.
// ---------------------------------------------------------------------------
struct SrcPair { const float* a; int la; const float* b; int lb; };

template <typename F>
__device__ __forceinline__ void gemm_main(uint32_t sb, const uint32_t* smu,
                                          int KT, F fetch_src,
                                          int wm, int wn, int gid, int tig,
                                          float c[16][4]) {
    auto saddr = [&](int st, int ab) {
        return sb + (uint32_t)(((st * 2 + ab) * TILE_WORDS) * 4);
    };
#pragma unroll
    for (int p = 0; p < STG - 1; ++p) {
        if (p < KT) {
            SrcPair s = fetch_src(p);
            cp_tile(saddr(p, 0), s.a, s.la);
            cp_tile(saddr(p, 1), s.b, s.lb);
        }
        CP_COMMIT();
    }
    int rs = 0;  // read stage
    for (int kt = 0; kt < KT; ++kt) {
        CP_WAIT1();
        __syncthreads();
        int pf = kt + STG - 1;
        if (pf < KT) {
            int ws = rs + STG - 1;
            if (ws >= STG) ws -= STG;
            SrcPair s = fetch_src(pf);
            cp_tile(saddr(ws, 0), s.a, s.la);
            cp_tile(saddr(ws, 1), s.b, s.lb);
        }
        CP_COMMIT();
        const uint32_t* As = smu + (size_t)rs * 2 * TILE_WORDS;
        const uint32_t* Bs = As + TILE_WORDS;
#pragma unroll
        for (int ko = 0; ko < BK; ko += 8)
            mma_oct(As, Bs, ko, wm, wn, gid, tig, c);
        if (++rs == STG) rs = 0;
    }
}

// ---------------------------------------------------------------------------
// K1: RoPE -> g_qr (t,n) and g_qt (n,t), tf32-rounded
// ---------------------------------------------------------------------------
__global__ void rope_kernel(const float* __restrict__ Q,
                            const float* __restrict__ C,
                            const float* __restrict__ S) {
    __shared__ float tile[32][65];
    const int bh = blockIdx.z, t0 = blockIdx.y * 32, n0 = blockIdx.x * 64;
    const int tid = threadIdx.x;
    const size_t qbase = ((size_t)bh * Tn + t0) * Nn + n0;
#pragma unroll
    for (int i = 0; i < 4; ++i) {
        int p  = tid + i * 256;
        int tt = p >> 5, pi = p & 31;
        int nn = pi * 2;
        float2 q = *reinterpret_cast<const float2*>(Q + qbase + (size_t)tt * Nn + nn);
        float2 c = *reinterpret_cast<const float2*>(C + (size_t)(t0 + tt) * Nn + n0 + nn);
        float2 s = *reinterpret_cast<const float2*>(S + (size_t)(t0 + tt) * Nn + n0 + nn);
        float2 r;
        r.x = f2tf(q.x * c.x - q.y * s.x);
        r.y = f2tf(q.y * c.y + q.x * s.y);
        *reinterpret_cast<float2*>(g_qr + qbase + (size_t)tt * Nn + nn) = r;
        tile[tt][nn] = r.x;
        tile[tt][nn + 1] = r.y;
    }
    __syncthreads();
    const size_t tbase = ((size_t)bh * Nn + n0) * Tn + t0;
#pragma unroll
    for (int i = 0; i < 8; ++i) {
        int e  = tid + i * 256;
        int nn = e >> 5, tt = e & 31;
        g_qt[tbase + (size_t)nn * Tn + tt] = tile[tt][nn];
    }
}

// K1b: state^T (d,n), tf32-rounded
__global__ void stateT_kernel(const float* __restrict__ St) {
    __shared__ float tile[32][33];
    const int bh = blockIdx.z, n0 = blockIdx.x * 32, d0 = blockIdx.y * 32;
    const int tid = threadIdx.x;
#pragma unroll
    for (int i = 0; i < 4; ++i) {
        int e = tid + i * 256;
        int nn = e >> 5, dd = e & 31;
        tile[nn][dd] = St[((size_t)bh * Nn + n0 + nn) * Dn + d0 + dd];
    }
    __syncthreads();
#pragma unroll
    for (int i = 0; i < 4; ++i) {
        int e = tid + i * 256;
        int dd = e >> 5, nn = e & 31;
        g_st[((size_t)bh * Dn + d0 + dd) * Nn + n0 + nn] = f2tf(tile[nn][dd]);
    }
}

// K1c: V^T (d,t), tf32-rounded
__global__ void vT_kernel(const float* __restrict__ V) {
    __shared__ float tile[32][33];
    const int b = blockIdx.z, t0 = blockIdx.x * 32, d0 = blockIdx.y * 32;
    const int tid = threadIdx.x;
#pragma unroll
    for (int i = 0; i < 4; ++i) {
        int e = tid + i * 256;
        int tt = e >> 5, dd = e & 31;
        tile[tt][dd] = V[((size_t)b * Tn + t0 + tt) * Dn + d0 + dd];
    }
    __syncthreads();
#pragma unroll
    for (int i = 0; i < 4; ++i) {
        int e = tid + i * 256;
        int dd = e >> 5, tt = e & 31;
        g_vt[((size_t)b * Dn + d0 + dd) * Tn + t0 + tt] = f2tf(tile[tt][dd]);
    }
}

// ---------------------------------------------------------------------------
// MEGA1: grid (288). Blocks 0..159: scores tiles (lower-tri).
//        Blocks 160..287: out_a = QR @ state  -> g_oa.
// All CTAs: K = 8192, uniform cost, one full wave on 296 slots.
// ---------------------------------------------------------------------------
__global__ void __launch_bounds__(256, 2) mega1_gemm() {
    extern __shared__ uint32_t smu[];
    uint32_t sb = smem_u32(smu);

    const int bid = blockIdx.x;
    const int lane = threadIdx.x & 31, wid = threadIdx.x >> 5;
    const int gid = lane >> 2, tig = lane & 3;
    const int wm = (wid & 1) * 64, wn = (wid >> 1) * 32;

    float c[16][4] = {};

    if (bid < 160) {
        // ---- scores tile ----
        const int bh = bid & 15, q = bid >> 4;
        const int tb = TRI_T[q], sb_ = TRI_S[q];
        const int t0 = tb * BM, s0 = sb_ * BM;
        const float* Asrc = g_qr + ((size_t)bh * Tn + t0) * Nn;
        const float* Bsrc = g_qr + ((size_t)bh * Tn + s0) * Nn;

        gemm_main(sb, smu, Nn / BK,
                  [&](int kt) { return SrcPair{Asrc + kt * BK, Nn, Bsrc + kt * BK, Nn}; },
                  wm, wn, gid, tig, c);

        float* Sc = g_sc + (size_t)bh * Tn * Tn;
#pragma unroll
        for (int im = 0; im < 4; ++im)
#pragma unroll
            for (int jn = 0; jn < 4; ++jn) {
                int t = t0 + wm + im * 16 + gid;
                int s = s0 + wn + jn * 8 + tig * 2;
                float* cc = c[im * 4 + jn];
                Sc[(size_t)t * Tn + s]           = (s     < t) ? f2tf(cc[0] * SCALEF) : 0.f;
                Sc[(size_t)t * Tn + s + 1]       = (s + 1 < t) ? f2tf(cc[1] * SCALEF) : 0.f;
                Sc[(size_t)(t + 8) * Tn + s]     = (s     < t + 8) ? f2tf(cc[2] * SCALEF) : 0.f;
                Sc[(size_t)(t + 8) * Tn + s + 1] = (s + 1 < t + 8) ? f2tf(cc[3] * SCALEF) : 0.f;
            }
    } else {
        // ---- out_a = QR @ state ----
        const int r = bid - 160;
        const int db = r & 1, tb = (r >> 1) & 3, bh = r >> 3;
        const int t0 = tb * BM, d0 = db * BM;
        const float* Asrc = g_qr + ((size_t)bh * Tn + t0) * Nn;
        const float* Bsrc = g_st + ((size_t)bh * Dn + d0) * Nn;

        gemm_main(sb, smu, Nn / BK,
                  [&](int kt) { return SrcPair{Asrc + kt * BK, Nn, Bsrc + kt * BK, Nn}; },
                  wm, wn, gid, tig, c);

        float* O = g_oa + ((size_t)bh * Tn + t0) * Dn + d0;
#pragma unroll
        for (int im = 0; im < 4; ++im)
#pragma unroll
            for (int jn = 0; jn < 4; ++jn) {
                int rr = wm + im * 16 + gid;
                int cN = wn + jn * 8 + tig * 2;
                float* cc = c[im * 4 + jn];
                O[(size_t)rr * Dn + cN]           = cc[0];
                O[(size_t)rr * Dn + cN + 1]       = cc[1];
                O[(size_t)(rr + 8) * Dn + cN]     = cc[2];
                O[(size_t)(rr + 8) * Dn + cN + 1] = cc[3];
            }
    }
}

// ---------------------------------------------------------------------------
// MEGA2: grid (2176). Blocks 0..127: out = scores@V + g_oa.
//        Blocks 128..2175: new_state = state + SCALE * QR^T @ V.
// ---------------------------------------------------------------------------
__global__ void __launch_bounds__(256, 2) mega2_gemm(const float* __restrict__ state,
                                                     float* __restrict__ out,
                                                     float* __restrict__ outns) {
    extern __shared__ uint32_t smu[];
    uint32_t sb = smem_u32(smu);

    const int bid = blockIdx.x;
    const int lane = threadIdx.x & 31, wid = threadIdx.x >> 5;
    const int gid = lane >> 2, tig = lane & 3;
    const int wm = (wid & 1) * 64, wn = (wid >> 1) * 32;

    float c[16][4] = {};

    if (bid < 128) {
        // ---- out = scores @ V + out_a ----
        const int db = bid & 1, tb = (bid >> 1) & 3, bh = bid >> 3, b = bh >> 2;
        const int t0 = tb * BM, d0 = db * BM;
        const float* Asrc = g_sc + ((size_t)bh * Tn + t0) * Tn;
        const float* Bsrc = g_vt + ((size_t)b * Dn + d0) * Tn;
        const int KT = (tb + 1) * (BM / BK);  // causal trim

        gemm_main(sb, smu, KT,
                  [&](int kt) { return SrcPair{Asrc + kt * BK, Tn, Bsrc + kt * BK, Tn}; },
                  wm, wn, gid, tig, c);

        const float* P = g_oa + ((size_t)bh * Tn + t0) * Dn + d0;
        float* O = out + ((size_t)bh * Tn + t0) * Dn + d0;
#pragma unroll
        for (int im = 0; im < 4; ++im)
#pragma unroll
            for (int jn = 0; jn < 4; ++jn) {
                int rr = wm + im * 16 + gid;
                int cN = wn + jn * 8 + tig * 2;
                float* cc = c[im * 4 + jn];
                O[(size_t)rr * Dn + cN]           = cc[0] + P[(size_t)rr * Dn + cN];
                O[(size_t)rr * Dn + cN + 1]       = cc[1] + P[(size_t)rr * Dn + cN + 1];
                O[(size_t)(rr + 8) * Dn + cN]     = cc[2] + P[(size_t)(rr + 8) * Dn + cN];
                O[(size_t)(rr + 8) * Dn + cN + 1] = cc[3] + P[(size_t)(rr + 8) * Dn + cN + 1];
            }
    } else {
        // ---- new_state ----
        const int r = bid - 128;
        const int db = r & 1, nb = (r >> 1) & 63, bh = r >> 7, b = bh >> 2;
        const int n0 = nb * BM, d0 = db * BM;
        const float* Asrc = g_qt + ((size_t)bh * Nn + n0) * Tn;
        const float* Bsrc = g_vt + ((size_t)b * Dn + d0) * Tn;

        gemm_main(sb, smu, Tn / BK,
                  [&](int kt) { return SrcPair{Asrc + kt * BK, Tn, Bsrc + kt * BK, Tn}; },
                  wm, wn, gid, tig, c);

        const float* St = state + ((size_t)bh * Nn + n0) * Dn + d0;
        float* O = outns + ((size_t)bh * Nn + n0) * Dn + d0;
#pragma unroll
        for (int im = 0; im < 4; ++im)
#pragma unroll
            for (int jn = 0; jn < 4; ++jn) {
                int rr = wm + im * 16 + gid;
                int cN = wn + jn * 8 + tig * 2;
                float* cc = c[im * 4 + jn];
                O[(size_t)rr * Dn + cN]           = St[(size_t)rr * Dn + cN]           + SCALEF * cc[0];
                O[(size_t)rr * Dn + cN + 1]       = St[(size_t)rr * Dn + cN + 1]       + SCALEF * cc[1];
                O[(size_t)(rr + 8) * Dn + cN]     = St[(size_t)(rr + 8) * Dn + cN]     + SCALEF * cc[2];
                O[(size_t)(rr + 8) * Dn + cN + 1] = St[(size_t)(rr + 8) * Dn + cN + 1] + SCALEF * cc[3];
            }
    }
}

}  // namespace

extern "C" void kernel_launch(void* const* d_in, const int* in_sizes, int n_in,
                              void* d_out, int out_size) {
    const float* Q     = (const float*)d_in[0];
    const float* V     = (const float*)d_in[1];
    const float* state = (const float*)d_in[2];
    const float* cosb  = (const float*)d_in[3];
    const float* sinb  = (const float*)d_in[4];
    float* out = (float*)d_out;

    cudaFuncSetAttribute(mega1_gemm, cudaFuncAttributeMaxDynamicSharedMemorySize, SMEM_TOTAL);
    cudaFuncSetAttribute(mega2_gemm, cudaFuncAttributeMaxDynamicSharedMemorySize, SMEM_TOTAL);

    rope_kernel<<<dim3(Nn / 64, Tn / 32, BHn), 256>>>(Q, cosb, sinb);
    stateT_kernel<<<dim3(Nn / 32, Dn / 32, BHn), 256>>>(state);
    vT_kernel<<<dim3(Tn / 32, Dn / 32, Bz), 256>>>(V);

    mega1_gemm<<<288, 256, SMEM_TOTAL>>>();
    mega2_gemm<<<2176, 256, SMEM_TOTAL>>>(state, out, out + (size_t)BHn * Tn * Dn);
}

// round 14
// speedup vs baseline: 1.0188x; 1.0188x over previous
#include <cuda_runtime.h>
#include <cstdint>

namespace {

constexpr int Bz  = 4;
constexpr int NHn = 4;
constexpr int Tn  = 512;
constexpr int Dn  = 256;
constexpr int Nn  = 8192;
constexpr int BHn = Bz * NHn;
constexpr float SCALEF = 0.011048543456039806f;  // N^-0.5

// Scratch (device globals; allocation-free). All values tf32-pre-rounded fp32.
__device__ float g_qr[(size_t)BHn * Tn * Nn];   // RoPE(Q)    (t,n)
__device__ float g_qt[(size_t)BHn * Nn * Tn];   // RoPE(Q)^T  (n,t)
__device__ float g_st[(size_t)BHn * Dn * Nn];   // state^T    (d,n)
__device__ float g_vt[(size_t)Bz * Dn * Tn];    // V^T        (d,t)
__device__ float g_sc[(size_t)BHn * Tn * Tn];   // masked scores (t,s)

// ---------------------------------------------------------------------------
// Tiling: BM=BN=128, BK=32. SMEM tiles [128 rows][36 words].
// 512 threads = 16 warps as 4(m) x 4(n); warp tile 32x32.
// 5-stage cp.async pipeline (wait_group 3 -> 3 tiles of latency coverage),
// 1 CTA per SM.
// ---------------------------------------------------------------------------
constexpr int BM = 128, BK = 32;
constexpr int RSTR = 36;
constexpr int TILE_WORDS = BM * RSTR;            // 4608
constexpr int STG = 5;
constexpr int SMEM_TOTAL = STG * 2 * TILE_WORDS * 4;   // 184320 B
constexpr int NT = 512;

__device__ __forceinline__ uint32_t f2t(float x) {
    uint32_t u;
    asm("cvt.rna.tf32.f32 %0, %1;" : "=r"(u) : "f"(x));
    return u;
}
__device__ __forceinline__ float f2tf(float x) { return __uint_as_float(f2t(x)); }

__device__ __forceinline__ uint32_t smem_u32(const void* p) {
    uint32_t a;
    asm("{ .reg .u64 t; cvta.to.shared.u64 t, %1; cvt.u32.u64 %0, t; }"
        : "=r"(a) : "l"(p));
    return a;
}

__device__ __forceinline__ void mma_tf32(float c[4], const uint32_t a[4],
                                         const uint32_t b[2]) {
    asm volatile(
        "mma.sync.aligned.m16n8k8.row.col.f32.tf32.tf32.f32 "
        "{%0,%1,%2,%3}, {%4,%5,%6,%7}, {%8,%9}, {%0,%1,%2,%3};"
        : "+f"(c[0]), "+f"(c[1]), "+f"(c[2]), "+f"(c[3])
        : "r"(a[0]), "r"(a[1]), "r"(a[2]), "r"(a[3]), "r"(b[0]), "r"(b[1]));
}

// One k-octet of the 32x32 warp tile. A,B both [128][36] row-major.
__device__ __forceinline__ void mma_oct(const uint32_t* __restrict__ As,
                                        const uint32_t* __restrict__ Bs,
                                        int ko, int wm, int wn,
                                        int gid, int tig, float c[8][4]) {
    uint32_t a[2][4], b[4][2];
#pragma unroll
    for (int im = 0; im < 2; ++im) {
        const uint32_t* pa = As + (wm + im * 16 + gid) * RSTR + ko + tig;
        a[im][0] = pa[0];
        a[im][1] = pa[8 * RSTR];
        a[im][2] = pa[4];
        a[im][3] = pa[8 * RSTR + 4];
    }
#pragma unroll
    for (int jn = 0; jn < 4; ++jn) {
        const uint32_t* pb = Bs + (wn + jn * 8 + gid) * RSTR + ko + tig;
        b[jn][0] = pb[0];
        b[jn][1] = pb[4];
    }
#pragma unroll
    for (int im = 0; im < 2; ++im)
#pragma unroll
        for (int jn = 0; jn < 4; ++jn)
            mma_tf32(c[im * 4 + jn], a[im], b[jn]);
}

// cp.async one [128][32] fp32 tile (k contiguous in source, row stride ld).
// 512 threads: 2 x 16B chunks per thread.
__device__ __forceinline__ void cp_tile(uint32_t dbase,
                                        const float* __restrict__ src, int ld) {
#pragma unroll
    for (int i = 0; i < 2; ++i) {
        int ch = threadIdx.x + i * NT;
        int row = ch >> 3, kc = (ch & 7) * 4;
        uint32_t d = dbase + (uint32_t)((row * RSTR + kc) * 4);
        asm volatile("cp.async.cg.shared.global [%0], [%1], 16;"
                     :: "r"(d), "l"(src + (size_t)row * ld + kc));
    }
}
#define CP_COMMIT() asm volatile("cp.async.commit_group;" ::: "memory")
#define CP_WAIT3()  asm volatile("cp.async.wait_group 3;" ::: "memory")

// ---------------------------------------------------------------------------
// Shared GEMM mainloop driver. Fetch(kt) -> {A ptr, lda, B ptr, ldb}.
// ---------------------------------------------------------------------------
struct SrcPair { const float* a; int la; const float* b; int lb; };

template <typename F>
__device__ __forceinline__ void gemm_main(uint32_t sb, const uint32_t* smu,
                                          int KT, F fetch_src,
                                          int wm, int wn, int gid, int tig,
                                          float c[8][4]) {
    auto saddr = [&](int st, int ab) {
        return sb + (uint32_t)(((st * 2 + ab) * TILE_WORDS) * 4);
    };
#pragma unroll
    for (int p = 0; p < STG - 1; ++p) {
        if (p < KT) {
            SrcPair s = fetch_src(p);
            cp_tile(saddr(p, 0), s.a, s.la);
            cp_tile(saddr(p, 1), s.b, s.lb);
        }
        CP_COMMIT();
    }
    int rs = 0;  // read stage
    for (int kt = 0; kt < KT; ++kt) {
        CP_WAIT3();
        __syncthreads();
        int pf = kt + STG - 1;
        if (pf < KT) {
            int ws = rs + STG - 1;
            if (ws >= STG) ws -= STG;
            SrcPair s = fetch_src(pf);
            cp_tile(saddr(ws, 0), s.a, s.la);
            cp_tile(saddr(ws, 1), s.b, s.lb);
        }
        CP_COMMIT();
        const uint32_t* As = smu + (size_t)rs * 2 * TILE_WORDS;
        const uint32_t* Bs = As + TILE_WORDS;
#pragma unroll
        for (int ko = 0; ko < BK; ko += 8)
            mma_oct(As, Bs, ko, wm, wn, gid, tig, c);
        if (++rs == STG) rs = 0;
    }
}

// ---------------------------------------------------------------------------
// K1: RoPE -> g_qr (t,n) and g_qt (n,t), tf32-rounded
// ---------------------------------------------------------------------------
__global__ void rope_kernel(const float* __restrict__ Q,
                            const float* __restrict__ C,
                            const float* __restrict__ S) {
    __shared__ float tile[32][65];
    const int bh = blockIdx.z, t0 = blockIdx.y * 32, n0 = blockIdx.x * 64;
    const int tid = threadIdx.x;
    const size_t qbase = ((size_t)bh * Tn + t0) * Nn + n0;
#pragma unroll
    for (int i = 0; i < 4; ++i) {
        int p  = tid + i * 256;
        int tt = p >> 5, pi = p & 31;
        int nn = pi * 2;
        float2 q = *reinterpret_cast<const float2*>(Q + qbase + (size_t)tt * Nn + nn);
        float2 c = *reinterpret_cast<const float2*>(C + (size_t)(t0 + tt) * Nn + n0 + nn);
        float2 s = *reinterpret_cast<const float2*>(S + (size_t)(t0 + tt) * Nn + n0 + nn);
        float2 r;
        r.x = f2tf(q.x * c.x - q.y * s.x);
        r.y = f2tf(q.y * c.y + q.x * s.y);
        *reinterpret_cast<float2*>(g_qr + qbase + (size_t)tt * Nn + nn) = r;
        tile[tt][nn] = r.x;
        tile[tt][nn + 1] = r.y;
    }
    __syncthreads();
    const size_t tbase = ((size_t)bh * Nn + n0) * Tn + t0;
#pragma unroll
    for (int i = 0; i < 8; ++i) {
        int e  = tid + i * 256;
        int nn = e >> 5, tt = e & 31;
        g_qt[tbase + (size_t)nn * Tn + tt] = tile[tt][nn];
    }
}

// K1b: state^T (d,n), tf32-rounded
__global__ void stateT_kernel(const float* __restrict__ St) {
    __shared__ float tile[32][33];
    const int bh = blockIdx.z, n0 = blockIdx.x * 32, d0 = blockIdx.y * 32;
    const int tid = threadIdx.x;
#pragma unroll
    for (int i = 0; i < 4; ++i) {
        int e = tid + i * 256;
        int nn = e >> 5, dd = e & 31;
        tile[nn][dd] = St[((size_t)bh * Nn + n0 + nn) * Dn + d0 + dd];
    }
    __syncthreads();
#pragma unroll
    for (int i = 0; i < 4; ++i) {
        int e = tid + i * 256;
        int dd = e >> 5, nn = e & 31;
        g_st[((size_t)bh * Dn + d0 + dd) * Nn + n0 + nn] = f2tf(tile[nn][dd]);
    }
}

// K1c: V^T (d,t), tf32-rounded
__global__ void vT_kernel(const float* __restrict__ V) {
    __shared__ float tile[32][33];
    const int b = blockIdx.z, t0 = blockIdx.x * 32, d0 = blockIdx.y * 32;
    const int tid = threadIdx.x;
#pragma unroll
    for (int i = 0; i < 4; ++i) {
        int e = tid + i * 256;
        int tt = e >> 5, dd = e & 31;
        tile[tt][dd] = V[((size_t)b * Tn + t0 + tt) * Dn + d0 + dd];
    }
    __syncthreads();
#pragma unroll
    for (int i = 0; i < 4; ++i) {
        int e = tid + i * 256;
        int dd = e >> 5, tt = e & 31;
        g_vt[((size_t)b * Dn + d0 + dd) * Tn + t0 + tt] = f2tf(tile[tt][dd]);
    }
}

// ---------------------------------------------------------------------------
// K2: scores = mask(QR @ QR^T) * SCALE (lower-tri tiles only), tf32-rounded
// grid (4, 4, 16)
// ---------------------------------------------------------------------------
__global__ void __launch_bounds__(NT, 1) scores_gemm() {
    const int sb_ = blockIdx.x, tb = blockIdx.y, bh = blockIdx.z;
    if (sb_ > tb) return;
    extern __shared__ uint32_t smu[];
    uint32_t sb = smem_u32(smu);

    const int t0 = tb * BM, s0 = sb_ * BM;
    const int lane = threadIdx.x & 31, wid = threadIdx.x >> 5;
    const int gid = lane >> 2, tig = lane & 3;
    const int wm = (wid & 3) * 32, wn = (wid >> 2) * 32;
    const float* Asrc = g_qr + ((size_t)bh * Tn + t0) * Nn;
    const float* Bsrc = g_qr + ((size_t)bh * Tn + s0) * Nn;

    float c[8][4] = {};
    gemm_main(sb, smu, Nn / BK,
              [&](int kt) { return SrcPair{Asrc + kt * BK, Nn, Bsrc + kt * BK, Nn}; },
              wm, wn, gid, tig, c);

    float* Sc = g_sc + (size_t)bh * Tn * Tn;
#pragma unroll
    for (int im = 0; im < 2; ++im)
#pragma unroll
        for (int jn = 0; jn < 4; ++jn) {
            int t = t0 + wm + im * 16 + gid;
            int s = s0 + wn + jn * 8 + tig * 2;
            float* cc = c[im * 4 + jn];
            Sc[(size_t)t * Tn + s]           = (s     < t) ? f2tf(cc[0] * SCALEF) : 0.f;
            Sc[(size_t)t * Tn + s + 1]       = (s + 1 < t) ? f2tf(cc[1] * SCALEF) : 0.f;
            Sc[(size_t)(t + 8) * Tn + s]     = (s     < t + 8) ? f2tf(cc[2] * SCALEF) : 0.f;
            Sc[(size_t)(t + 8) * Tn + s + 1] = (s + 1 < t + 8) ? f2tf(cc[3] * SCALEF) : 0.f;
        }
}

// ---------------------------------------------------------------------------
// K3: out = scores @ V + QR @ state  (two K-segments, one accumulator)
// grid (2, 4, 16)
// ---------------------------------------------------------------------------
__global__ void __launch_bounds__(NT, 1) out_gemm(float* __restrict__ out) {
    extern __shared__ uint32_t smu[];
    uint32_t sb = smem_u32(smu);

    const int db = blockIdx.x, tb = blockIdx.y, bh = blockIdx.z, b = bh >> 2;
    const int t0 = tb * BM, d0 = db * BM;
    const int lane = threadIdx.x & 31, wid = threadIdx.x >> 5;
    const int gid = lane >> 2, tig = lane & 3;
    const int wm = (wid & 3) * 32, wn = (wid >> 2) * 32;

    const float* A1 = g_sc + ((size_t)bh * Tn + t0) * Tn;
    const float* B1 = g_vt + ((size_t)b * Dn + d0) * Tn;
    const float* A2 = g_qr + ((size_t)bh * Tn + t0) * Nn;
    const float* B2 = g_st + ((size_t)bh * Dn + d0) * Nn;

    const int KT1 = (tb + 1) * (BM / BK);   // causal trim
    const int KT = KT1 + Nn / BK;

    float c[8][4] = {};
    gemm_main(sb, smu, KT,
              [&](int kt) {
                  if (kt < KT1)
                      return SrcPair{A1 + kt * BK, Tn, B1 + kt * BK, Tn};
                  int k2 = kt - KT1;
                  return SrcPair{A2 + k2 * BK, Nn, B2 + k2 * BK, Nn};
              },
              wm, wn, gid, tig, c);

    float* O = out + ((size_t)bh * Tn + t0) * Dn + d0;
#pragma unroll
    for (int im = 0; im < 2; ++im)
#pragma unroll
        for (int jn = 0; jn < 4; ++jn) {
            int r = wm + im * 16 + gid;
            int cN = wn + jn * 8 + tig * 2;
            float* cc = c[im * 4 + jn];
            O[(size_t)r * Dn + cN]           = cc[0];
            O[(size_t)r * Dn + cN + 1]       = cc[1];
            O[(size_t)(r + 8) * Dn + cN]     = cc[2];
            O[(size_t)(r + 8) * Dn + cN + 1] = cc[3];
        }
}

// ---------------------------------------------------------------------------
// K4: new_state = state + SCALE * QR^T @ V
// grid (2, 64, 16)
// ---------------------------------------------------------------------------
__global__ void __launch_bounds__(NT, 1) nstate_gemm(const float* __restrict__ state,
                                                     float* __restrict__ outns) {
    extern __shared__ uint32_t smu[];
    uint32_t sb = smem_u32(smu);

    const int db = blockIdx.x, nb = blockIdx.y, bh = blockIdx.z, b = bh >> 2;
    const int n0 = nb * BM, d0 = db * BM;
    const int lane = threadIdx.x & 31, wid = threadIdx.x >> 5;
    const int gid = lane >> 2, tig = lane & 3;
    const int wm = (wid & 3) * 32, wn = (wid >> 2) * 32;

    const float* Asrc = g_qt + ((size_t)bh * Nn + n0) * Tn;
    const float* Bsrc = g_vt + ((size_t)b * Dn + d0) * Tn;

    float c[8][4] = {};
    gemm_main(sb, smu, Tn / BK,
              [&](int kt) { return SrcPair{Asrc + kt * BK, Tn, Bsrc + kt * BK, Tn}; },
              wm, wn, gid, tig, c);

    const float* St = state + ((size_t)bh * Nn + n0) * Dn + d0;
    float* O = outns + ((size_t)bh * Nn + n0) * Dn + d0;
#pragma unroll
    for (int im = 0; im < 2; ++im)
#pragma unroll
        for (int jn = 0; jn < 4; ++jn) {
            int r = wm + im * 16 + gid;
            int cN = wn + jn * 8 + tig * 2;
            float* cc = c[im * 4 + jn];
            O[(size_t)r * Dn + cN]           = St[(size_t)r * Dn + cN]           + SCALEF * cc[0];
            O[(size_t)r * Dn + cN + 1]       = St[(size_t)r * Dn + cN + 1]       + SCALEF * cc[1];
            O[(size_t)(r + 8) * Dn + cN]     = St[(size_t)(r + 8) * Dn + cN]     + SCALEF * cc[2];
            O[(size_t)(r + 8) * Dn + cN + 1] = St[(size_t)(r + 8) * Dn + cN + 1] + SCALEF * cc[3];
        }
}

}  // namespace

extern "C" void kernel_launch(void* const* d_in, const int* in_sizes, int n_in,
                              void* d_out, int out_size) {
    const float* Q     = (const float*)d_in[0];
    const float* V     = (const float*)d_in[1];
    const float* state = (const float*)d_in[2];
    const float* cosb  = (const float*)d_in[3];
    const float* sinb  = (const float*)d_in[4];
    float* out = (float*)d_out;

    cudaFuncSetAttribute(scores_gemm, cudaFuncAttributeMaxDynamicSharedMemorySize, SMEM_TOTAL);
    cudaFuncSetAttribute(out_gemm,    cudaFuncAttributeMaxDynamicSharedMemorySize, SMEM_TOTAL);
    cudaFuncSetAttribute(nstate_gemm, cudaFuncAttributeMaxDynamicSharedMemorySize, SMEM_TOTAL);

    rope_kernel<<<dim3(Nn / 64, Tn / 32, BHn), 256>>>(Q, cosb, sinb);
    stateT_kernel<<<dim3(Nn / 32, Dn / 32, BHn), 256>>>(state);
    vT_kernel<<<dim3(Tn / 32, Dn / 32, Bz), 256>>>(V);

    scores_gemm<<<dim3(4, 4, BHn), NT, SMEM_TOTAL>>>();
    out_gemm<<<dim3(2, 4, BHn), NT, SMEM_TOTAL>>>(out);
    nstate_gemm<<<dim3(2, Nn / BM, BHn), NT, SMEM_TOTAL>>>(
        state, out + (size_t)BHn * Tn * Dn);
}

// round 16
// speedup vs baseline: 1.2081x; 1.1858x over previous
#include <cuda_runtime.h>
#include <cstdint>

namespace {

constexpr int Bz  = 4;
constexpr int NHn = 4;
constexpr int Tn  = 512;
constexpr int Dn  = 256;
constexpr int Nn  = 8192;
constexpr int BHn = Bz * NHn;
constexpr float SCALEF = 0.011048543456039806f;  // N^-0.5

// Scratch (device globals; allocation-free). All values tf32-pre-rounded fp32.
__device__ float g_qr[(size_t)BHn * Tn * Nn];   // RoPE(Q)    (t,n)
__device__ float g_qt[(size_t)BHn * Nn * Tn];   // RoPE(Q)^T  (n,t)
__device__ float g_st[(size_t)BHn * Dn * Nn];   // state^T    (d,n)
__device__ float g_vt[(size_t)Bz * Dn * Tn];    // V^T        (d,t)
__device__ float g_sc[(size_t)BHn * Tn * Tn];   // masked scores (t,s)
__device__ float g_oa[(size_t)BHn * Tn * Dn];   // partial out: QR @ state

// ---------------------------------------------------------------------------
// Tiling: CTA tile 128(m) x 256(n), BK=32. 8 warps as 2(m) x 4(n);
// warp tile 64x64 (c[32][4] -> high smem reuse; MMA-bound not smem-bound).
// SMEM rows [36 words]; A tile [128][36], B tile [256][36] (both k-contig).
// 3-stage cp.async pipeline, 1 CTA/SM.
// ---------------------------------------------------------------------------
constexpr int BM = 128, BN = 256, BK = 32;
constexpr int RSTR = 36;
constexpr int A_WORDS = BM * RSTR;               // 4608
constexpr int B_WORDS = BN * RSTR;               // 9216
constexpr int STAGE_WORDS = A_WORDS + B_WORDS;   // 13824
constexpr int STG = 3;
constexpr int SMEM_TOTAL = STG * STAGE_WORDS * 4;  // 165888 B
constexpr int NT = 256;

__device__ __forceinline__ uint32_t f2t(float x) {
    uint32_t u;
    asm("cvt.rna.tf32.f32 %0, %1;" : "=r"(u) : "f"(x));
    return u;
}
__device__ __forceinline__ float f2tf(float x) { return __uint_as_float(f2t(x)); }

__device__ __forceinline__ uint32_t smem_u32(const void* p) {
    uint32_t a;
    asm("{ .reg .u64 t; cvta.to.shared.u64 t, %1; cvt.u32.u64 %0, t; }"
        : "=r"(a) : "l"(p));
    return a;
}

__device__ __forceinline__ void mma_tf32(float c[4], const uint32_t a[4],
                                         const uint32_t b[2]) {
    asm volatile(
        "mma.sync.aligned.m16n8k8.row.col.f32.tf32.tf32.f32 "
        "{%0,%1,%2,%3}, {%4,%5,%6,%7}, {%8,%9}, {%0,%1,%2,%3};"
        : "+f"(c[0]), "+f"(c[1]), "+f"(c[2]), "+f"(c[3])
        : "r"(a[0]), "r"(a[1]), "r"(a[2]), "r"(a[3]), "r"(b[0]), "r"(b[1]));
}

// One k-octet of the 64x64 warp tile.
__device__ __forceinline__ void mma_oct(const uint32_t* __restrict__ As,
                                        const uint32_t* __restrict__ Bs,
                                        int ko, int wm, int wn,
                                        int gid, int tig, float c[32][4]) {
    uint32_t a[4][4], b[8][2];
#pragma unroll
    for (int im = 0; im < 4; ++im) {
        const uint32_t* pa = As + (wm + im * 16 + gid) * RSTR + ko + tig;
        a[im][0] = pa[0];
        a[im][1] = pa[8 * RSTR];
        a[im][2] = pa[4];
        a[im][3] = pa[8 * RSTR + 4];
    }
#pragma unroll
    for (int jn = 0; jn < 8; ++jn) {
        const uint32_t* pb = Bs + (wn + jn * 8 + gid) * RSTR + ko + tig;
        b[jn][0] = pb[0];
        b[jn][1] = pb[4];
    }
#pragma unroll
    for (int im = 0; im < 4; ++im)
#pragma unroll
        for (int jn = 0; jn < 8; ++jn)
            mma_tf32(c[im * 8 + jn], a[im], b[jn]);
}

// cp.async tiles (k contiguous in source, row stride ld). 256 threads.
__device__ __forceinline__ void cp_A(uint32_t dbase,
                                     const float* __restrict__ src, int ld) {
#pragma unroll
    for (int i = 0; i < 4; ++i) {
        int ch = threadIdx.x + i * NT;
        int row = ch >> 3, kc = (ch & 7) * 4;
        uint32_t d = dbase + (uint32_t)((row * RSTR + kc) * 4);
        asm volatile("cp.async.cg.shared.global [%0], [%1], 16;"
                     :: "r"(d), "l"(src + (size_t)row * ld + kc));
    }
}
__device__ __forceinline__ void cp_B(uint32_t dbase,
                                     const float* __restrict__ src, int ld) {
#pragma unroll
    for (int i = 0; i < 8; ++i) {
        int ch = threadIdx.x + i * NT;
        int row = ch >> 3, kc = (ch & 7) * 4;
        uint32_t d = dbase + (uint32_t)((row * RSTR + kc) * 4);
        asm volatile("cp.async.cg.shared.global [%0], [%1], 16;"
                     :: "r"(d), "l"(src + (size_t)row * ld + kc));
    }
}
#define CP_COMMIT() asm volatile("cp.async.commit_group;" ::: "memory")
#define CP_WAIT1()  asm volatile("cp.async.wait_group 1;" ::: "memory")

// ---------------------------------------------------------------------------
// Shared GEMM mainloop. Fetch(kt) -> {A ptr, lda, B ptr, ldb}.
// ---------------------------------------------------------------------------
struct SrcPair { const float* a; int la; const float* b; int lb; };

template <typename F>
__device__ __forceinline__ void gemm_main(uint32_t sb, const uint32_t* smu,
                                          int KT, F fetch_src,
                                          int wm, int wn, int gid, int tig,
                                          float c[32][4]) {
    auto abase = [&](int st) { return sb + (uint32_t)(st * STAGE_WORDS * 4); };
#pragma unroll
    for (int p = 0; p < STG - 1; ++p) {
        if (p < KT) {
            SrcPair s = fetch_src(p);
            cp_A(abase(p), s.a, s.la);
            cp_B(abase(p) + A_WORDS * 4, s.b, s.lb);
        }
        CP_COMMIT();
    }
    int rs = 0;
    for (int kt = 0; kt < KT; ++kt) {
        CP_WAIT1();
        __syncthreads();
        int pf = kt + STG - 1;
        if (pf < KT) {
            int ws = rs + STG - 1;
            if (ws >= STG) ws -= STG;
            SrcPair s = fetch_src(pf);
            cp_A(abase(ws), s.a, s.la);
            cp_B(abase(ws) + A_WORDS * 4, s.b, s.lb);
        }
        CP_COMMIT();
        const uint32_t* As = smu + (size_t)rs * STAGE_WORDS;
        const uint32_t* Bs = As + A_WORDS;
#pragma unroll
        for (int ko = 0; ko < BK; ko += 8)
            mma_oct(As, Bs, ko, wm, wn, gid, tig, c);
        if (++rs == STG) rs = 0;
    }
}

// ---------------------------------------------------------------------------
// Prepasses (unchanged numerics)
// ---------------------------------------------------------------------------
__global__ void rope_kernel(const float* __restrict__ Q,
                            const float* __restrict__ C,
                            const float* __restrict__ S) {
    __shared__ float tile[32][65];
    const int bh = blockIdx.z, t0 = blockIdx.y * 32, n0 = blockIdx.x * 64;
    const int tid = threadIdx.x;
    const size_t qbase = ((size_t)bh * Tn + t0) * Nn + n0;
#pragma unroll
    for (int i = 0; i < 4; ++i) {
        int p  = tid + i * 256;
        int tt = p >> 5, pi = p & 31;
        int nn = pi * 2;
        float2 q = *reinterpret_cast<const float2*>(Q + qbase + (size_t)tt * Nn + nn);
        float2 c = *reinterpret_cast<const float2*>(C + (size_t)(t0 + tt) * Nn + n0 + nn);
        float2 s = *reinterpret_cast<const float2*>(S + (size_t)(t0 + tt) * Nn + n0 + nn);
        float2 r;
        r.x = f2tf(q.x * c.x - q.y * s.x);
        r.y = f2tf(q.y * c.y + q.x * s.y);
        *reinterpret_cast<float2*>(g_qr + qbase + (size_t)tt * Nn + nn) = r;
        tile[tt][nn] = r.x;
        tile[tt][nn + 1] = r.y;
    }
    __syncthreads();
    const size_t tbase = ((size_t)bh * Nn + n0) * Tn + t0;
#pragma unroll
    for (int i = 0; i < 8; ++i) {
        int e  = tid + i * 256;
        int nn = e >> 5, tt = e & 31;
        g_qt[tbase + (size_t)nn * Tn + tt] = tile[tt][nn];
    }
}

__global__ void stateT_kernel(const float* __restrict__ St) {
    __shared__ float tile[32][33];
    const int bh = blockIdx.z, n0 = blockIdx.x * 32, d0 = blockIdx.y * 32;
    const int tid = threadIdx.x;
#pragma unroll
    for (int i = 0; i < 4; ++i) {
        int e = tid + i * 256;
        int nn = e >> 5, dd = e & 31;
        tile[nn][dd] = St[((size_t)bh * Nn + n0 + nn) * Dn + d0 + dd];
    }
    __syncthreads();
#pragma unroll
    for (int i = 0; i < 4; ++i) {
        int e = tid + i * 256;
        int dd = e >> 5, nn = e & 31;
        g_st[((size_t)bh * Dn + d0 + dd) * Nn + n0 + nn] = f2tf(tile[nn][dd]);
    }
}

__global__ void vT_kernel(const float* __restrict__ V) {
    __shared__ float tile[32][33];
    const int b = blockIdx.z, t0 = blockIdx.x * 32, d0 = blockIdx.y * 32;
    const int tid = threadIdx.x;
#pragma unroll
    for (int i = 0; i < 4; ++i) {
        int e = tid + i * 256;
        int tt = e >> 5, dd = e & 31;
        tile[tt][dd] = V[((size_t)b * Tn + t0 + tt) * Dn + d0 + dd];
    }
    __syncthreads();
#pragma unroll
    for (int i = 0; i < 4; ++i) {
        int e = tid + i * 256;
        int dd = e >> 5, tt = e & 31;
        g_vt[((size_t)b * Dn + d0 + dd) * Tn + t0 + tt] = f2tf(tile[tt][dd]);
    }
}

// ---------------------------------------------------------------------------
// MEGA: grid 1184.
//  bid [0,96):     scores tiles (lower-tri, 128x256), K=8192 -> g_sc
//  bid [96,160):   out_a = QR @ state (128x256), K=8192      -> g_oa
//  bid [160,1184): new_state (128x256), K=512                -> outns
// ---------------------------------------------------------------------------
__global__ void __launch_bounds__(NT, 1) mega_gemm(const float* __restrict__ state,
                                                   float* __restrict__ outns) {
    extern __shared__ uint32_t smu[];
    uint32_t sb = smem_u32(smu);

    const int bid = blockIdx.x;
    const int lane = threadIdx.x & 31, wid = threadIdx.x >> 5;
    const int gid = lane >> 2, tig = lane & 3;
    const int wm = (wid & 1) * 64, wn = (wid >> 1) * 64;

    float c[32][4] = {};

    if (bid < 96) {
        // ---- scores ----
        // lower-tri (tb, sb) pairs for 128-row x 256-col tiles:
        constexpr int TRI_T[6] = {0, 1, 2, 2, 3, 3};
        constexpr int TRI_S[6] = {0, 0, 0, 1, 0, 1};
        const int bh = bid & 15, q = bid >> 4;
        const int t0 = TRI_T[q] * BM, s0 = TRI_S[q] * BN;
        const float* Asrc = g_qr + ((size_t)bh * Tn + t0) * Nn;
        const float* Bsrc = g_qr + ((size_t)bh * Tn + s0) * Nn;

        gemm_main(sb, smu, Nn / BK,
                  [&](int kt) { return SrcPair{Asrc + kt * BK, Nn, Bsrc + kt * BK, Nn}; },
                  wm, wn, gid, tig, c);

        float* Sc = g_sc + (size_t)bh * Tn * Tn;
#pragma unroll
        for (int im = 0; im < 4; ++im)
#pragma unroll
            for (int jn = 0; jn < 8; ++jn) {
                int t = t0 + wm + im * 16 + gid;
                int s = s0 + wn + jn * 8 + tig * 2;
                float* cc = c[im * 8 + jn];
                Sc[(size_t)t * Tn + s]           = (s     < t) ? f2tf(cc[0] * SCALEF) : 0.f;
                Sc[(size_t)t * Tn + s + 1]       = (s + 1 < t) ? f2tf(cc[1] * SCALEF) : 0.f;
                Sc[(size_t)(t + 8) * Tn + s]     = (s     < t + 8) ? f2tf(cc[2] * SCALEF) : 0.f;
                Sc[(size_t)(t + 8) * Tn + s + 1] = (s + 1 < t + 8) ? f2tf(cc[3] * SCALEF) : 0.f;
            }
    } else if (bid < 160) {
        // ---- out_a = QR @ state (d covers full 256) ----
        const int r = bid - 96;
        const int tb = r & 3, bh = r >> 2;
        const int t0 = tb * BM;
        const float* Asrc = g_qr + ((size_t)bh * Tn + t0) * Nn;
        const float* Bsrc = g_st + (size_t)bh * Dn * Nn;

        gemm_main(sb, smu, Nn / BK,
                  [&](int kt) { return SrcPair{Asrc + kt * BK, Nn, Bsrc + kt * BK, Nn}; },
                  wm, wn, gid, tig, c);

        float* O = g_oa + ((size_t)bh * Tn + t0) * Dn;
#pragma unroll
        for (int im = 0; im < 4; ++im)
#pragma unroll
            for (int jn = 0; jn < 8; ++jn) {
                int rr = wm + im * 16 + gid;
                int cN = wn + jn * 8 + tig * 2;
                float* cc = c[im * 8 + jn];
                O[(size_t)rr * Dn + cN]           = cc[0];
                O[(size_t)rr * Dn + cN + 1]       = cc[1];
                O[(size_t)(rr + 8) * Dn + cN]     = cc[2];
                O[(size_t)(rr + 8) * Dn + cN + 1] = cc[3];
            }
    } else {
        // ---- new_state ----
        const int r = bid - 160;
        const int nb = r & 63, bh = r >> 6, b = bh >> 2;
        const int n0 = nb * BM;
        const float* Asrc = g_qt + ((size_t)bh * Nn + n0) * Tn;
        const float* Bsrc = g_vt + (size_t)b * Dn * Tn;

        gemm_main(sb, smu, Tn / BK,
                  [&](int kt) { return SrcPair{Asrc + kt * BK, Tn, Bsrc + kt * BK, Tn}; },
                  wm, wn, gid, tig, c);

        const float* St = state + ((size_t)bh * Nn + n0) * Dn;
        float* O = outns + ((size_t)bh * Nn + n0) * Dn;
#pragma unroll
        for (int im = 0; im < 4; ++im)
#pragma unroll
            for (int jn = 0; jn < 8; ++jn) {
                int rr = wm + im * 16 + gid;
                int cN = wn + jn * 8 + tig * 2;
                float* cc = c[im * 8 + jn];
                O[(size_t)rr * Dn + cN]           = St[(size_t)rr * Dn + cN]           + SCALEF * cc[0];
                O[(size_t)rr * Dn + cN + 1]       = St[(size_t)rr * Dn + cN + 1]       + SCALEF * cc[1];
                O[(size_t)(rr + 8) * Dn + cN]     = St[(size_t)(rr + 8) * Dn + cN]     + SCALEF * cc[2];
                O[(size_t)(rr + 8) * Dn + cN + 1] = St[(size_t)(rr + 8) * Dn + cN + 1] + SCALEF * cc[3];
            }
    }
}

// ---------------------------------------------------------------------------
// OUT_B: out = scores @ V + g_oa. grid 64 (tb 4 x bh 16), K = (tb+1)*128.
// ---------------------------------------------------------------------------
__global__ void __launch_bounds__(NT, 1) outb_gemm(float* __restrict__ out) {
    extern __shared__ uint32_t smu[];
    uint32_t sb = smem_u32(smu);

    const int bid = blockIdx.x;
    const int tb = bid & 3, bh = bid >> 2, b = bh >> 2;
    const int t0 = tb * BM;
    const int lane = threadIdx.x & 31, wid = threadIdx.x >> 5;
    const int gid = lane >> 2, tig = lane & 3;
    const int wm = (wid & 1) * 64, wn = (wid >> 1) * 64;

    const float* Asrc = g_sc + ((size_t)bh * Tn + t0) * Tn;
    const float* Bsrc = g_vt + (size_t)b * Dn * Tn;
    const int KT = (tb + 1) * (BM / BK);

    float c[32][4] = {};
    gemm_main(sb, smu, KT,
              [&](int kt) { return SrcPair{Asrc + kt * BK, Tn, Bsrc + kt * BK, Tn}; },
              wm, wn, gid, tig, c);

    const float* P = g_oa + ((size_t)bh * Tn + t0) * Dn;
    float* O = out + ((size_t)bh * Tn + t0) * Dn;
#pragma unroll
    for (int im = 0; im < 4; ++im)
#pragma unroll
        for (int jn = 0; jn < 8; ++jn) {
            int rr = wm + im * 16 + gid;
            int cN = wn + jn * 8 + tig * 2;
            float* cc = c[im * 8 + jn];
            O[(size_t)rr * Dn + cN]           = cc[0] + P[(size_t)rr * Dn + cN];
            O[(size_t)rr * Dn + cN + 1]       = cc[1] + P[(size_t)rr * Dn + cN + 1];
            O[(size_t)(rr + 8) * Dn + cN]     = cc[2] + P[(size_t)(rr + 8) * Dn + cN];
            O[(size_t)(rr + 8) * Dn + cN + 1] = cc[3] + P[(size_t)(rr + 8) * Dn + cN + 1];
        }
}

}  // namespace

extern "C" void kernel_launch(void* const* d_in, const int* in_sizes, int n_in,
                              void* d_out, int out_size) {
    const float* Q     = (const float*)d_in[0];
    const float* V     = (const float*)d_in[1];
    const float* state = (const float*)d_in[2];
    const float* cosb  = (const float*)d_in[3];
    const float* sinb  = (const float*)d_in[4];
    float* out = (float*)d_out;

    cudaFuncSetAttribute(mega_gemm, cudaFuncAttributeMaxDynamicSharedMemorySize, SMEM_TOTAL);
    cudaFuncSetAttribute(outb_gemm, cudaFuncAttributeMaxDynamicSharedMemorySize, SMEM_TOTAL);

    rope_kernel<<<dim3(Nn / 64, Tn / 32, BHn), 256>>>(Q, cosb, sinb);
    stateT_kernel<<<dim3(Nn / 32, Dn / 32, BHn), 256>>>(state);
    vT_kernel<<<dim3(Tn / 32, Dn / 32, Bz), 256>>>(V);

    mega_gemm<<<1184, NT, SMEM_TOTAL>>>(state, out + (size_t)BHn * Tn * Dn);
    outb_gemm<<<64, NT, SMEM_TOTAL>>>(out);
}